// round 13
// baseline (speedup 1.0000x reference)
#include <cuda_runtime.h>
#include <cuda_fp16.h>
#include <math_constants.h>
#include <cstdint>

// Problem constants (B=2, T=2048, C=2048, H=16, D=128)
#define BB   2
#define TT   2048
#define CC   2048
#define HH   16
#define DD   128
#define MTOT (BB*TT)          // 4096
#define N3C  (3*CC)           // 6144
#define KDIM 2048

typedef __half fp16;

// -------- scratch (static device globals: the allowed scratch path) --------
__device__ fp16 g_q[(size_t)BB*HH*TT*DD];    // q pre-scaled by 1/sqrt(d)
__device__ fp16 g_k[(size_t)BB*HH*TT*DD];
__device__ fp16 g_v[(size_t)BB*HH*TT*DD];
__device__ fp16 g_x[(size_t)MTOT*KDIM];      // x as fp16
__device__ fp16 g_y[(size_t)MTOT*KDIM];      // attention out as fp16
__device__ fp16 g_wq[(size_t)N3C*KDIM];      // w_attn^T [N][K] fp16
__device__ fp16 g_wp[(size_t)CC*KDIM];       // w_proj^T [N][K] fp16

// ============================================================================
// helpers
// ============================================================================
__device__ __forceinline__ uint32_t smem_u32(const void* p) {
    uint32_t a;
    asm("{ .reg .u64 t; cvta.to.shared.u64 t, %1; cvt.u32.u64 %0, t; }"
        : "=r"(a) : "l"(p));
    return a;
}
// (fp16(a) in low 16) | (fp16(b) in high 16)
__device__ __forceinline__ uint32_t pack2_f16(float a, float b) {
    uint32_t r;
    asm("cvt.rn.f16x2.f32 %0, %1, %2;" : "=r"(r) : "f"(b), "f"(a));
    return r;
}
#define CP16(dst, src) \
    asm volatile("cp.async.cg.shared.global [%0], [%1], 16;" \
                 :: "r"(dst), "l"(src))
#define CP_COMMIT() asm volatile("cp.async.commit_group;")
#define CP_WAIT(n)  asm volatile("cp.async.wait_group %0;" :: "n"(n))

__device__ __forceinline__ void ldsm_x4(uint32_t* r, uint32_t addr) {
    asm volatile("ldmatrix.sync.aligned.m8n8.x4.shared.b16 {%0,%1,%2,%3}, [%4];"
        : "=r"(r[0]), "=r"(r[1]), "=r"(r[2]), "=r"(r[3]) : "r"(addr));
}
__device__ __forceinline__ void ldsm_x4_t(uint32_t* r, uint32_t addr) {
    asm volatile("ldmatrix.sync.aligned.m8n8.x4.trans.shared.b16 {%0,%1,%2,%3}, [%4];"
        : "=r"(r[0]), "=r"(r[1]), "=r"(r[2]), "=r"(r[3]) : "r"(addr));
}
__device__ __forceinline__ void ldsm_x2(uint32_t* r, uint32_t addr) {
    asm volatile("ldmatrix.sync.aligned.m8n8.x2.shared.b16 {%0,%1}, [%2];"
        : "=r"(r[0]), "=r"(r[1]) : "r"(addr));
}
__device__ __forceinline__ void mma16816(float* c, const uint32_t* a,
                                         const uint32_t* b) {
    asm volatile(
        "mma.sync.aligned.m16n8k16.row.col.f32.f16.f16.f32 "
        "{%0,%1,%2,%3}, {%4,%5,%6,%7}, {%8,%9}, {%0,%1,%2,%3};"
        : "+f"(c[0]), "+f"(c[1]), "+f"(c[2]), "+f"(c[3])
        : "r"(a[0]), "r"(a[1]), "r"(a[2]), "r"(a[3]), "r"(b[0]), "r"(b[1]));
}

// ============================================================================
// Prep kernels
// ============================================================================
__global__ __launch_bounds__(256) void conv_x_kernel(
    const float* __restrict__ X, fp16* __restrict__ O)
{
    size_t i4 = (size_t)blockIdx.x * 256 + threadIdx.x;
    float4 v = ((const float4*)X)[i4];
    uint32_t lo = pack2_f16(v.x, v.y);
    uint32_t hi = pack2_f16(v.z, v.w);
    *(uint2*)(O + i4 * 4) = make_uint2(lo, hi);
}

// W [K][N] fp32 -> W^T [N][K] fp16. Tile 64k x 32n.
__global__ __launch_bounds__(256) void prep_w_kernel(
    const float* __restrict__ W, fp16* __restrict__ O, int N)
{
    __shared__ float s[32][65];           // [n][k] transposed
    const int k0 = blockIdx.y * 64;
    const int n0 = blockIdx.x * 32;
    const int tid = threadIdx.x;
    const int nn = tid & 31, kk = tid >> 5;
#pragma unroll
    for (int i = 0; i < 8; i++) {
        int k = kk + i * 8;
        s[nn][k] = __ldg(W + (size_t)(k0 + k) * N + n0 + nn);
    }
    __syncthreads();
    const int n = tid >> 3, kc = (tid & 7) * 8;
    uint32_t o4[4];
#pragma unroll
    for (int j = 0; j < 4; j++)
        o4[j] = pack2_f16(s[n][kc + 2*j], s[n][kc + 2*j + 1]);
    size_t o = (size_t)(n0 + n) * KDIM + k0 + kc;
    *(uint4*)(O + o) = *(uint4*)o4;
}

// ============================================================================
// fp16 GEMM via mma.sync: C[M,N] = A[M,K] @ B^T[N,K]
// 128x128x64 CTA tile, 8 warps (2x4), warp tile 64x32, 2 CTAs/SM,
// single-sync double-buffered cp.async (round-8 config — measured best).
// MODE 0: scatter into g_q/g_k/g_v (fp16, q pre-scaled); MODE 1: fp32 Cout.
// ============================================================================
#define GPITCH 144            // 64 fp16 = 128B + 16B pad
#define BOFF   18432          // 128 rows * 144B
#define STG    36864          // A + B
#define GEMM_SMEM (2*STG)     // 73728
#define NCHUNK (KDIM/64)      // 32

template<int MODE>
__global__ __launch_bounds__(256, 2) void gemm_fp16_kernel(
    const fp16* __restrict__ A, const fp16* __restrict__ B,
    float* __restrict__ Cout)
{
    extern __shared__ char smem[];
    const uint32_t sb = smem_u32(smem);
    const int tid  = threadIdx.x;
    const int lane = tid & 31, wid = tid >> 5;
    const int wm = wid & 1, wn = wid >> 1;       // warp grid 2 x 4
    const int m0 = blockIdx.y * 128;
    const int n0 = blockIdx.x * 128;

    float acc[4][4][4];
#pragma unroll
    for (int mi = 0; mi < 4; mi++)
#pragma unroll
        for (int ni = 0; ni < 4; ni++)
#pragma unroll
            for (int f = 0; f < 4; f++) acc[mi][ni][f] = 0.f;

    const uint32_t aBase = sb + (wm * 64 + (lane & 15)) * GPITCH
                         + (lane >> 4) * 16;
    const uint32_t bBase = sb + BOFF + (wn * 32 + (lane & 7)) * GPITCH
                         + ((lane >> 3) & 1) * 16;

#define LOAD_CHUNK(c, st) do {                                                 \
    uint32_t s0 = sb + (st) * STG;                                             \
    _Pragma("unroll")                                                          \
    for (int p = 0; p < 4; p++) {                                              \
        int o   = tid + p * 256;          /* 0..1023 */                        \
        int row = o >> 3, ch = o & 7;                                          \
        uint32_t dofs = row * GPITCH + ch * 16;                                \
        size_t ga = (size_t)(m0 + row) * KDIM + (c) * 64 + ch * 8;             \
        size_t gb = (size_t)(n0 + row) * KDIM + (c) * 64 + ch * 8;             \
        CP16(s0 + dofs, A + ga);                                               \
        CP16(s0 + BOFF + dofs, B + gb);                                        \
    }                                                                          \
} while (0)

    LOAD_CHUNK(0, 0);
    CP_COMMIT();

    for (int c = 0; c < NCHUNK; c++) {
        const int st = c & 1;
        CP_WAIT(0);               // chunk c resident
        __syncthreads();          // stage st^1 fully consumed by all warps
        if (c + 1 < NCHUNK) {     // overlap next chunk's loads with MMA(c)
            LOAD_CHUNK(c + 1, st ^ 1);
            CP_COMMIT();
        }

        const uint32_t sStage = st * STG;
#pragma unroll
        for (int ks = 0; ks < 4; ks++) {
            const uint32_t kOfs = sStage + ks * 32;
            uint32_t aw[4][4], bw[4][2];
#pragma unroll
            for (int mi = 0; mi < 4; mi++)
                ldsm_x4(aw[mi], aBase + kOfs + mi * (16 * GPITCH));
#pragma unroll
            for (int ni = 0; ni < 4; ni++)
                ldsm_x2(bw[ni], bBase + kOfs + ni * (8 * GPITCH));
#pragma unroll
            for (int mi = 0; mi < 4; mi++)
#pragma unroll
                for (int ni = 0; ni < 4; ni++)
                    mma16816(acc[mi][ni], aw[mi], bw[ni]);
        }
    }

    // ---- epilogue ----
    const int lr = lane >> 2, lc = (lane & 3) * 2;
#pragma unroll
    for (int mi = 0; mi < 4; mi++) {
#pragma unroll
        for (int ni = 0; ni < 4; ni++) {
            int mrow = m0 + wm * 64 + mi * 16 + lr;
            int col  = wn * 32 + ni * 8 + lc;
            if (MODE == 0) {
                const int nb = blockIdx.x;
                const int which = nb >> 4, head = nb & 15;
                const float sc = (which == 0) ? 0.08838834764831845f : 1.0f;
                fp16* base = (which == 0) ? g_q : (which == 1) ? g_k : g_v;
                int b0 = mrow >> 11, t0 = mrow & 2047;
                int m1 = mrow + 8;
                int b1 = m1 >> 11, t1 = m1 & 2047;
                size_t i0 = ((size_t)((b0 * HH + head) * TT + t0)) * DD + col;
                size_t i1 = ((size_t)((b1 * HH + head) * TT + t1)) * DD + col;
                *(uint32_t*)(base + i0) =
                    pack2_f16(acc[mi][ni][0] * sc, acc[mi][ni][1] * sc);
                *(uint32_t*)(base + i1) =
                    pack2_f16(acc[mi][ni][2] * sc, acc[mi][ni][3] * sc);
            } else {
                float* p0 = Cout + (size_t)mrow * CC + n0 + col;
                float* p1 = p0 + (size_t)8 * CC;
                *(float2*)p0 = make_float2(acc[mi][ni][0], acc[mi][ni][1]);
                *(float2*)p1 = make_float2(acc[mi][ni][2], acc[mi][ni][3]);
            }
        }
    }
#undef LOAD_CHUNK
}

// ============================================================================
// Flash attention on mma.sync (fp16). BM=64, BN=128 (wide K tile), D=128,
// 4 warps, 2 CTAs/SM. K double-buffered (128-row tiles); V(kb2) + K(kb2+1)
// issued at iter start, hidden under S. Fully-masked 16-col blocks on the
// diagonal tile are skipped via uniform predicates.
// ============================================================================
#define FA_PITCH 272        // bytes per 128-fp16 row (256 + 16 pad)
#define FA_K0 0
#define FA_K1 34816         // 128 rows * 272
#define FA_V  69632
#define FA_SMEM 104448      // x2 CTAs = 208896 <= 228KB carveout

__global__ __launch_bounds__(128, 2) void flash_attn_mma_kernel()
{
    extern __shared__ char smc[];
    const uint32_t sb = smem_u32(smc);
    const int tid  = threadIdx.x;
    const int lane = tid & 31, wid = tid >> 5;
    const int qb = (int)(gridDim.x - 1 - blockIdx.x);   // longest CTAs first
    const int bh = blockIdx.y;

    const size_t bhofs = (size_t)bh * TT * DD;
    const fp16* Qg = g_q + bhofs + (size_t)qb * 64 * DD;

    // ---- stage Q (64 rows) into K1 region; preload K tile 0 (128 rows)
#pragma unroll
    for (int p = 0; p < 8; p++) {
        int o = tid + p * 128;
        int row = o >> 4, ch = o & 15;
        CP16(sb + FA_K1 + row * FA_PITCH + ch * 16,
             Qg + (size_t)row * DD + ch * 8);
    }
#pragma unroll
    for (int p = 0; p < 16; p++) {
        int o = tid + p * 128;
        int row = o >> 4, ch = o & 15;
        CP16(sb + FA_K0 + row * FA_PITCH + ch * 16,
             g_k + bhofs + (size_t)row * DD + ch * 8);
    }
    CP_COMMIT();
    CP_WAIT(0);
    __syncthreads();

    uint32_t qf[8][4];
    {
        uint32_t qa = sb + FA_K1 + (wid * 16 + (lane & 15)) * FA_PITCH
                    + (lane >> 4) * 16;
#pragma unroll
        for (int ks = 0; ks < 8; ks++)
            ldsm_x4(qf[ks], qa + ks * 32);
    }
    __syncthreads();     // everyone holds Q in regs; K1 free for K tile 1

    float yacc[16][4];
#pragma unroll
    for (int n = 0; n < 16; n++)
#pragma unroll
        for (int f = 0; f < 4; f++) yacc[n][f] = 0.f;
    float m0r = -CUDART_INF_F, m1r = -CUDART_INF_F;
    float l0r = 0.f, l1r = 0.f;

    const int r0 = lane >> 2;
    const int c0 = (lane & 3) * 2;

    const uint32_t laneK = ((lane & 7) + ((lane >> 4) & 1) * 8) * FA_PITCH
                         + ((lane >> 3) & 1) * 16;
    const uint32_t vaddr = sb + FA_V
        + ((lane & 7) + ((lane >> 3) & 1) * 8) * FA_PITCH
        + ((lane >> 4) & 1) * 16;

    const int nk = (qb >> 1) + 1;        // 128-wide K tiles
    const int rowmax = 64 * qb + 63;

    for (int kb2 = 0; kb2 < nk; kb2++) {
        const uint32_t kaddr = sb + ((kb2 & 1) ? FA_K1 : FA_K0) + laneK;
        const int kend = rowmax - 128 * kb2;   // last valid col in this tile

        __syncthreads();   // PV(kb2-1) consumed; V region + next-K buffer free
        {
            const fp16* Vg = g_v + bhofs + (size_t)kb2 * 128 * DD;
#pragma unroll
            for (int p = 0; p < 16; p++) {
                int o = tid + p * 128;
                int row = o >> 4, ch = o & 15;
                CP16(sb + FA_V + row * FA_PITCH + ch * 16,
                     Vg + (size_t)row * DD + ch * 8);
            }
            if (kb2 + 1 < nk) {
                const uint32_t knext = sb + (((kb2 + 1) & 1) ? FA_K1 : FA_K0);
                const fp16* Kg = g_k + bhofs + (size_t)(kb2 + 1) * 128 * DD;
#pragma unroll
                for (int p = 0; p < 16; p++) {
                    int o = tid + p * 128;
                    int row = o >> 4, ch = o & 15;
                    CP16(knext + row * FA_PITCH + ch * 16,
                         Kg + (size_t)row * DD + ch * 8);
                }
            }
            CP_COMMIT();
        }

        // ---- S = Q K^T on resident K(kb2); skip fully-masked 16-col blocks
        float s[16][4];
#pragma unroll
        for (int j = 0; j < 16; j++)
#pragma unroll
            for (int f = 0; f < 4; f++) s[j][f] = 0.f;

#pragma unroll
        for (int ks = 0; ks < 8; ks++) {
#pragma unroll
            for (int jj = 0; jj < 8; jj++) {
                if (jj * 16 <= kend) {
                    uint32_t kf[4];
                    ldsm_x4(kf, kaddr + jj * (16 * FA_PITCH) + ks * 32);
                    mma16816(s[2*jj],   qf[ks], kf);
                    mma16816(s[2*jj+1], qf[ks], kf + 2);
                }
            }
        }

        // ---- causal mask (diagonal tile only; q pre-scaled by 1/sqrt(d))
        if (kb2 == nk - 1) {
            const int rg0 = 64 * qb + wid * 16 + r0;
            const int cb  = 128 * kb2;
#pragma unroll
            for (int j = 0; j < 16; j++) {
                int cg = cb + j * 8 + c0;
                if (cg     > rg0)     s[j][0] = -CUDART_INF_F;
                if (cg + 1 > rg0)     s[j][1] = -CUDART_INF_F;
                if (cg     > rg0 + 8) s[j][2] = -CUDART_INF_F;
                if (cg + 1 > rg0 + 8) s[j][3] = -CUDART_INF_F;
            }
        }

        // ---- online softmax (rows r0, r0+8; 4-lane groups share a row)
        float mx0 = -CUDART_INF_F, mx1 = -CUDART_INF_F;
#pragma unroll
        for (int j = 0; j < 16; j++) {
            mx0 = fmaxf(mx0, fmaxf(s[j][0], s[j][1]));
            mx1 = fmaxf(mx1, fmaxf(s[j][2], s[j][3]));
        }
        mx0 = fmaxf(mx0, __shfl_xor_sync(0xffffffffu, mx0, 1));
        mx0 = fmaxf(mx0, __shfl_xor_sync(0xffffffffu, mx0, 2));
        mx1 = fmaxf(mx1, __shfl_xor_sync(0xffffffffu, mx1, 1));
        mx1 = fmaxf(mx1, __shfl_xor_sync(0xffffffffu, mx1, 2));

        float nm0 = fmaxf(m0r, mx0), nm1 = fmaxf(m1r, mx1);
        float co0 = __expf(m0r - nm0), co1 = __expf(m1r - nm1);
        m0r = nm0; m1r = nm1;

        uint32_t pp[16][2];
        float sl0 = 0.f, sl1 = 0.f;
#pragma unroll
        for (int j = 0; j < 16; j++) {
            float p00 = __expf(s[j][0] - nm0), p01 = __expf(s[j][1] - nm0);
            float p10 = __expf(s[j][2] - nm1), p11 = __expf(s[j][3] - nm1);
            sl0 += p00 + p01;  sl1 += p10 + p11;
            pp[j][0] = pack2_f16(p00, p01);
            pp[j][1] = pack2_f16(p10, p11);
        }
        sl0 += __shfl_xor_sync(0xffffffffu, sl0, 1);
        sl0 += __shfl_xor_sync(0xffffffffu, sl0, 2);
        sl1 += __shfl_xor_sync(0xffffffffu, sl1, 1);
        sl1 += __shfl_xor_sync(0xffffffffu, sl1, 2);
        l0r = l0r * co0 + sl0;
        l1r = l1r * co1 + sl1;
#pragma unroll
        for (int n = 0; n < 16; n++) {
            yacc[n][0] *= co0; yacc[n][1] *= co0;
            yacc[n][2] *= co1; yacc[n][3] *= co1;
        }

        // ---- V(kb2) resident; make visible
        CP_WAIT(0);
        __syncthreads();

        // ---- O += P V (skip fully-masked 16-row P chunks)
#pragma unroll
        for (int t = 0; t < 8; t++) {
            if (t * 16 <= kend) {
                uint32_t ap[4] = {pp[2*t][0], pp[2*t][1],
                                  pp[2*t+1][0], pp[2*t+1][1]};
#pragma unroll
                for (int half = 0; half < 2; half++) {
                    uint32_t vf[4][4];
#pragma unroll
                    for (int nn = 0; nn < 4; nn++)
                        ldsm_x4_t(vf[nn], vaddr + t * (16 * FA_PITCH)
                                          + (half * 4 + nn) * 32);
#pragma unroll
                    for (int nn = 0; nn < 4; nn++) {
                        int n2 = (half * 4 + nn) * 2;
                        mma16816(yacc[n2],     ap, vf[nn]);
                        mma16816(yacc[n2 + 1], ap, vf[nn] + 2);
                    }
                }
            }
        }
    }

    // ---- finalize: y/l as fp16 into [B,T,C] layout
    const float inv0 = 1.f / l0r, inv1 = 1.f / l1r;
    const int b = bh >> 4, h = bh & 15;
    const int t0 = qb * 64 + wid * 16 + r0;
    const size_t base0 = ((size_t)(b * TT + t0)) * CC + h * DD;
    const size_t base1 = base0 + (size_t)8 * CC;
#pragma unroll
    for (int n = 0; n < 16; n++) {
        int d0 = n * 8 + c0;
        *(uint32_t*)(g_y + base0 + d0) =
            pack2_f16(yacc[n][0] * inv0, yacc[n][1] * inv0);
        *(uint32_t*)(g_y + base1 + d0) =
            pack2_f16(yacc[n][2] * inv1, yacc[n][3] * inv1);
    }
}

// ============================================================================
extern "C" void kernel_launch(void* const* d_in, const int* in_sizes, int n_in,
                              void* d_out, int out_size)
{
    const float* x      = (const float*)d_in[0];   // [2,2048,2048]
    const float* w_attn = (const float*)d_in[1];   // [2048,6144]
    const float* w_proj = (const float*)d_in[2];   // [2048,2048]
    float* out = (float*)d_out;                    // [2,2048,2048]

    fp16 *xh, *yh, *wqh, *wph;
    cudaGetSymbolAddress((void**)&xh,  g_x);
    cudaGetSymbolAddress((void**)&yh,  g_y);
    cudaGetSymbolAddress((void**)&wqh, g_wq);
    cudaGetSymbolAddress((void**)&wph, g_wp);

    cudaFuncSetAttribute(gemm_fp16_kernel<0>,
                         cudaFuncAttributeMaxDynamicSharedMemorySize, GEMM_SMEM);
    cudaFuncSetAttribute(gemm_fp16_kernel<1>,
                         cudaFuncAttributeMaxDynamicSharedMemorySize, GEMM_SMEM);
    cudaFuncSetAttribute(flash_attn_mma_kernel,
                         cudaFuncAttributeMaxDynamicSharedMemorySize, FA_SMEM);

    // 0) prep: convert x, transpose+convert weights
    conv_x_kernel<<<(size_t)MTOT * KDIM / 4 / 256, 256>>>(x, xh);
    prep_w_kernel<<<dim3(N3C / 32, KDIM / 64), 256>>>(w_attn, wqh, N3C);
    prep_w_kernel<<<dim3(CC  / 32, KDIM / 64), 256>>>(w_proj, wph, CC);

    // 1) QKV projection -> fp16 q (pre-scaled), k, v  (round-8 config)
    gemm_fp16_kernel<0><<<dim3(N3C / 128, MTOT / 128), 256, GEMM_SMEM>>>(
        xh, wqh, nullptr);

    // 2) causal flash attention (mma.sync fp16, BN=128) -> g_y
    flash_attn_mma_kernel<<<dim3(TT / 64, BB * HH), 128, FA_SMEM>>>();

    // 3) output projection -> out (fp32)
    gemm_fp16_kernel<1><<<dim3(CC / 128, MTOT / 128), 256, GEMM_SMEM>>>(
        yh, wph, out);
}

// round 15
// speedup vs baseline: 1.0592x; 1.0592x over previous
#include <cuda_runtime.h>
#include <cuda_fp16.h>
#include <math_constants.h>
#include <cstdint>

// Problem constants (B=2, T=2048, C=2048, H=16, D=128)
#define BB   2
#define TT   2048
#define CC   2048
#define HH   16
#define DD   128
#define MTOT (BB*TT)          // 4096
#define N3C  (3*CC)           // 6144
#define KDIM 2048

typedef __half fp16;

// -------- scratch (static device globals: the allowed scratch path) --------
__device__ fp16 g_q[(size_t)BB*HH*TT*DD];    // q pre-scaled by 1/sqrt(d)
__device__ fp16 g_k[(size_t)BB*HH*TT*DD];
__device__ fp16 g_v[(size_t)BB*HH*TT*DD];
__device__ fp16 g_x[(size_t)MTOT*KDIM];      // x as fp16
__device__ fp16 g_y[(size_t)MTOT*KDIM];      // attention out as fp16
__device__ fp16 g_wq[(size_t)N3C*KDIM];      // w_attn^T [N][K] fp16
__device__ fp16 g_wp[(size_t)CC*KDIM];       // w_proj^T [N][K] fp16

// ============================================================================
// helpers
// ============================================================================
__device__ __forceinline__ uint32_t smem_u32(const void* p) {
    uint32_t a;
    asm("{ .reg .u64 t; cvta.to.shared.u64 t, %1; cvt.u32.u64 %0, t; }"
        : "=r"(a) : "l"(p));
    return a;
}
// (fp16(a) in low 16) | (fp16(b) in high 16)
__device__ __forceinline__ uint32_t pack2_f16(float a, float b) {
    uint32_t r;
    asm("cvt.rn.f16x2.f32 %0, %1, %2;" : "=r"(r) : "f"(b), "f"(a));
    return r;
}
#define CP16(dst, src) \
    asm volatile("cp.async.cg.shared.global [%0], [%1], 16;" \
                 :: "r"(dst), "l"(src))
#define CP_COMMIT() asm volatile("cp.async.commit_group;")
#define CP_WAIT(n)  asm volatile("cp.async.wait_group %0;" :: "n"(n))

__device__ __forceinline__ void ldsm_x4(uint32_t* r, uint32_t addr) {
    asm volatile("ldmatrix.sync.aligned.m8n8.x4.shared.b16 {%0,%1,%2,%3}, [%4];"
        : "=r"(r[0]), "=r"(r[1]), "=r"(r[2]), "=r"(r[3]) : "r"(addr));
}
__device__ __forceinline__ void ldsm_x4_t(uint32_t* r, uint32_t addr) {
    asm volatile("ldmatrix.sync.aligned.m8n8.x4.trans.shared.b16 {%0,%1,%2,%3}, [%4];"
        : "=r"(r[0]), "=r"(r[1]), "=r"(r[2]), "=r"(r[3]) : "r"(addr));
}
__device__ __forceinline__ void ldsm_x2(uint32_t* r, uint32_t addr) {
    asm volatile("ldmatrix.sync.aligned.m8n8.x2.shared.b16 {%0,%1}, [%2];"
        : "=r"(r[0]), "=r"(r[1]) : "r"(addr));
}
__device__ __forceinline__ void mma16816(float* c, const uint32_t* a,
                                         const uint32_t* b) {
    asm volatile(
        "mma.sync.aligned.m16n8k16.row.col.f32.f16.f16.f32 "
        "{%0,%1,%2,%3}, {%4,%5,%6,%7}, {%8,%9}, {%0,%1,%2,%3};"
        : "+f"(c[0]), "+f"(c[1]), "+f"(c[2]), "+f"(c[3])
        : "r"(a[0]), "r"(a[1]), "r"(a[2]), "r"(a[3]), "r"(b[0]), "r"(b[1]));
}

// ============================================================================
// Fused prep: ONE launch does x conversion + both weight transposes.
// Block ranges:  [0, 8192)          conv x -> g_x
//                [8192, 14336)      w_attn^T -> g_wq  (6144 blocks: 192 x 32)
//                [14336, 16384)     w_proj^T -> g_wp  (2048 blocks: 64 x 32)
// ============================================================================
#define PREP_CONV_BLKS 8192
#define PREP_WQ_BLKS   6144
#define PREP_WP_BLKS   2048
#define PREP_TOTAL     (PREP_CONV_BLKS + PREP_WQ_BLKS + PREP_WP_BLKS)

__device__ __forceinline__ void prep_w_body(
    const float* __restrict__ W, fp16* __restrict__ O, int N,
    int nblk, int kblk, int tid)
{
    __shared__ float s[32][65];           // [n][k] transposed
    const int k0 = kblk * 64;
    const int n0 = nblk * 32;
    const int nn = tid & 31, kk = tid >> 5;
#pragma unroll
    for (int i = 0; i < 8; i++) {
        int k = kk + i * 8;
        s[nn][k] = __ldg(W + (size_t)(k0 + k) * N + n0 + nn);
    }
    __syncthreads();
    const int n = tid >> 3, kc = (tid & 7) * 8;
    uint32_t o4[4];
#pragma unroll
    for (int j = 0; j < 4; j++)
        o4[j] = pack2_f16(s[n][kc + 2*j], s[n][kc + 2*j + 1]);
    size_t o = (size_t)(n0 + n) * KDIM + k0 + kc;
    *(uint4*)(O + o) = *(uint4*)o4;
}

__global__ __launch_bounds__(256) void prep_all_kernel(
    const float* __restrict__ X, const float* __restrict__ Wq,
    const float* __restrict__ Wp)
{
    const int b   = blockIdx.x;
    const int tid = threadIdx.x;
    if (b < PREP_CONV_BLKS) {
        size_t i4 = (size_t)b * 256 + tid;
        float4 v = ((const float4*)X)[i4];
        uint32_t lo = pack2_f16(v.x, v.y);
        uint32_t hi = pack2_f16(v.z, v.w);
        *(uint2*)(g_x + i4 * 4) = make_uint2(lo, hi);
    } else if (b < PREP_CONV_BLKS + PREP_WQ_BLKS) {
        int lb = b - PREP_CONV_BLKS;          // 0..6143
        prep_w_body(Wq, g_wq, N3C, lb % (N3C / 32), lb / (N3C / 32), tid);
    } else {
        int lb = b - PREP_CONV_BLKS - PREP_WQ_BLKS;   // 0..2047
        prep_w_body(Wp, g_wp, CC, lb % (CC / 32), lb / (CC / 32), tid);
    }
}

// ============================================================================
// fp16 GEMM via mma.sync: C[M,N] = A[M,K] @ B^T[N,K]
// 128x128x64 CTA tile, 8 warps (2x4), warp tile 64x32, 2 CTAs/SM,
// single-sync double-buffered cp.async (round-8 config — measured best).
// MODE 0: scatter into g_q/g_k/g_v (fp16, q pre-scaled); MODE 1: fp32 Cout.
// ============================================================================
#define GPITCH 144            // 64 fp16 = 128B + 16B pad
#define BOFF   18432          // 128 rows * 144B
#define STG    36864          // A + B
#define GEMM_SMEM (2*STG)     // 73728
#define NCHUNK (KDIM/64)      // 32

template<int MODE>
__global__ __launch_bounds__(256, 2) void gemm_fp16_kernel(
    const fp16* __restrict__ A, const fp16* __restrict__ B,
    float* __restrict__ Cout)
{
    extern __shared__ char smem[];
    const uint32_t sb = smem_u32(smem);
    const int tid  = threadIdx.x;
    const int lane = tid & 31, wid = tid >> 5;
    const int wm = wid & 1, wn = wid >> 1;       // warp grid 2 x 4
    const int m0 = blockIdx.y * 128;
    const int n0 = blockIdx.x * 128;

    float acc[4][4][4];
#pragma unroll
    for (int mi = 0; mi < 4; mi++)
#pragma unroll
        for (int ni = 0; ni < 4; ni++)
#pragma unroll
            for (int f = 0; f < 4; f++) acc[mi][ni][f] = 0.f;

    const uint32_t aBase = sb + (wm * 64 + (lane & 15)) * GPITCH
                         + (lane >> 4) * 16;
    const uint32_t bBase = sb + BOFF + (wn * 32 + (lane & 7)) * GPITCH
                         + ((lane >> 3) & 1) * 16;

#define LOAD_CHUNK(c, st) do {                                                 \
    uint32_t s0 = sb + (st) * STG;                                             \
    _Pragma("unroll")                                                          \
    for (int p = 0; p < 4; p++) {                                              \
        int o   = tid + p * 256;          /* 0..1023 */                        \
        int row = o >> 3, ch = o & 7;                                          \
        uint32_t dofs = row * GPITCH + ch * 16;                                \
        size_t ga = (size_t)(m0 + row) * KDIM + (c) * 64 + ch * 8;             \
        size_t gb = (size_t)(n0 + row) * KDIM + (c) * 64 + ch * 8;             \
        CP16(s0 + dofs, A + ga);                                               \
        CP16(s0 + BOFF + dofs, B + gb);                                        \
    }                                                                          \
} while (0)

    LOAD_CHUNK(0, 0);
    CP_COMMIT();

    for (int c = 0; c < NCHUNK; c++) {
        const int st = c & 1;
        CP_WAIT(0);               // chunk c resident
        __syncthreads();          // stage st^1 fully consumed by all warps
        if (c + 1 < NCHUNK) {     // overlap next chunk's loads with MMA(c)
            LOAD_CHUNK(c + 1, st ^ 1);
            CP_COMMIT();
        }

        const uint32_t sStage = st * STG;
#pragma unroll
        for (int ks = 0; ks < 4; ks++) {
            const uint32_t kOfs = sStage + ks * 32;
            uint32_t aw[4][4], bw[4][2];
#pragma unroll
            for (int mi = 0; mi < 4; mi++)
                ldsm_x4(aw[mi], aBase + kOfs + mi * (16 * GPITCH));
#pragma unroll
            for (int ni = 0; ni < 4; ni++)
                ldsm_x2(bw[ni], bBase + kOfs + ni * (8 * GPITCH));
#pragma unroll
            for (int mi = 0; mi < 4; mi++)
#pragma unroll
                for (int ni = 0; ni < 4; ni++)
                    mma16816(acc[mi][ni], aw[mi], bw[ni]);
        }
    }

    // ---- epilogue ----
    const int lr = lane >> 2, lc = (lane & 3) * 2;
#pragma unroll
    for (int mi = 0; mi < 4; mi++) {
#pragma unroll
        for (int ni = 0; ni < 4; ni++) {
            int mrow = m0 + wm * 64 + mi * 16 + lr;
            int col  = wn * 32 + ni * 8 + lc;
            if (MODE == 0) {
                const int nb = blockIdx.x;
                const int which = nb >> 4, head = nb & 15;
                const float sc = (which == 0) ? 0.08838834764831845f : 1.0f;
                fp16* base = (which == 0) ? g_q : (which == 1) ? g_k : g_v;
                int b0 = mrow >> 11, t0 = mrow & 2047;
                int m1 = mrow + 8;
                int b1 = m1 >> 11, t1 = m1 & 2047;
                size_t i0 = ((size_t)((b0 * HH + head) * TT + t0)) * DD + col;
                size_t i1 = ((size_t)((b1 * HH + head) * TT + t1)) * DD + col;
                *(uint32_t*)(base + i0) =
                    pack2_f16(acc[mi][ni][0] * sc, acc[mi][ni][1] * sc);
                *(uint32_t*)(base + i1) =
                    pack2_f16(acc[mi][ni][2] * sc, acc[mi][ni][3] * sc);
            } else {
                float* p0 = Cout + (size_t)mrow * CC + n0 + col;
                float* p1 = p0 + (size_t)8 * CC;
                *(float2*)p0 = make_float2(acc[mi][ni][0], acc[mi][ni][1]);
                *(float2*)p1 = make_float2(acc[mi][ni][2], acc[mi][ni][3]);
            }
        }
    }
#undef LOAD_CHUNK
}

// ============================================================================
// Flash attention on mma.sync (fp16). BM=BN=64, D=128, 4 warps, 2 CTAs/SM.
// K double-buffered; V(kb) + K(kb+1) issued at iter start, hidden under S.
// (exact round-8 version — measured best)
// ============================================================================
#define FA_PITCH 272        // bytes per 128-fp16 row (256 + 16 pad)
#define FA_K0 0
#define FA_K1 17408
#define FA_V  34816
#define FA_SMEM 52224

__global__ __launch_bounds__(128, 2) void flash_attn_mma_kernel()
{
    extern __shared__ char smc[];
    const uint32_t sb = smem_u32(smc);
    const int tid  = threadIdx.x;
    const int lane = tid & 31, wid = tid >> 5;
    const int qb = (int)(gridDim.x - 1 - blockIdx.x);   // longest CTAs first
    const int bh = blockIdx.y;

    const size_t bhofs = (size_t)bh * TT * DD;
    const fp16* Qg = g_q + bhofs + (size_t)qb * 64 * DD;

    // ---- stage Q into K1 region, preload K(0) into K0
#pragma unroll
    for (int p = 0; p < 8; p++) {
        int o = tid + p * 128;
        int row = o >> 4, ch = o & 15;
        uint32_t d = row * FA_PITCH + ch * 16;
        size_t g = (size_t)row * DD + ch * 8;
        CP16(sb + FA_K1 + d, Qg + g);
        CP16(sb + FA_K0 + d, g_k + bhofs + g);
    }
    CP_COMMIT();
    CP_WAIT(0);
    __syncthreads();

    uint32_t qf[8][4];
    {
        uint32_t qa = sb + FA_K1 + (wid * 16 + (lane & 15)) * FA_PITCH
                    + (lane >> 4) * 16;
#pragma unroll
        for (int ks = 0; ks < 8; ks++)
            ldsm_x4(qf[ks], qa + ks * 32);
    }

    float yacc[16][4];
#pragma unroll
    for (int n = 0; n < 16; n++)
#pragma unroll
        for (int f = 0; f < 4; f++) yacc[n][f] = 0.f;
    float m0r = -CUDART_INF_F, m1r = -CUDART_INF_F;
    float l0r = 0.f, l1r = 0.f;

    const int r0 = lane >> 2;
    const int c0 = (lane & 3) * 2;

    const uint32_t laneK = ((lane & 7) + ((lane >> 4) & 1) * 8) * FA_PITCH
                         + ((lane >> 3) & 1) * 16;
    const uint32_t vaddr = sb + FA_V
        + ((lane & 7) + ((lane >> 3) & 1) * 8) * FA_PITCH
        + ((lane >> 4) & 1) * 16;

    for (int kb = 0; kb <= qb; kb++) {
        const uint32_t kaddr = sb + ((kb & 1) ? FA_K1 : FA_K0) + laneK;

        __syncthreads();   // PV(kb-1) consumed; V region + next-K buffer free
        {
            const fp16* Vg = g_v + bhofs + (size_t)kb * 64 * DD;
#pragma unroll
            for (int p = 0; p < 8; p++) {
                int o = tid + p * 128;
                int row = o >> 4, ch = o & 15;
                uint32_t d = row * FA_PITCH + ch * 16;
                size_t g = (size_t)row * DD + ch * 8;
                CP16(sb + FA_V + d, Vg + g);
            }
            if (kb < qb) {
                const uint32_t knext = sb + (((kb + 1) & 1) ? FA_K1 : FA_K0);
                const fp16* Kg = g_k + bhofs + (size_t)(kb + 1) * 64 * DD;
#pragma unroll
                for (int p = 0; p < 8; p++) {
                    int o = tid + p * 128;
                    int row = o >> 4, ch = o & 15;
                    uint32_t d = row * FA_PITCH + ch * 16;
                    size_t g = (size_t)row * DD + ch * 8;
                    CP16(knext + d, Kg + g);
                }
            }
            CP_COMMIT();
        }

        // ---- S = Q K^T on resident K(kb)
        float s[8][4];
#pragma unroll
        for (int j = 0; j < 8; j++)
#pragma unroll
            for (int f = 0; f < 4; f++) s[j][f] = 0.f;

#pragma unroll
        for (int ks = 0; ks < 8; ks++) {
            uint32_t kf[4][4];
#pragma unroll
            for (int jj = 0; jj < 4; jj++)
                ldsm_x4(kf[jj], kaddr + jj * (16 * FA_PITCH) + ks * 32);
#pragma unroll
            for (int jj = 0; jj < 4; jj++) {
                mma16816(s[2*jj],   qf[ks], kf[jj]);
                mma16816(s[2*jj+1], qf[ks], kf[jj] + 2);
            }
        }

        // ---- causal mask + online softmax
        if (kb == qb) {
            const int rg0 = wid * 16 + r0;
#pragma unroll
            for (int j = 0; j < 8; j++) {
                int cg = j * 8 + c0;
                if (cg     > rg0)     s[j][0] = -CUDART_INF_F;
                if (cg + 1 > rg0)     s[j][1] = -CUDART_INF_F;
                if (cg     > rg0 + 8) s[j][2] = -CUDART_INF_F;
                if (cg + 1 > rg0 + 8) s[j][3] = -CUDART_INF_F;
            }
        }

        float mx0 = -CUDART_INF_F, mx1 = -CUDART_INF_F;
#pragma unroll
        for (int j = 0; j < 8; j++) {
            mx0 = fmaxf(mx0, fmaxf(s[j][0], s[j][1]));
            mx1 = fmaxf(mx1, fmaxf(s[j][2], s[j][3]));
        }
        mx0 = fmaxf(mx0, __shfl_xor_sync(0xffffffffu, mx0, 1));
        mx0 = fmaxf(mx0, __shfl_xor_sync(0xffffffffu, mx0, 2));
        mx1 = fmaxf(mx1, __shfl_xor_sync(0xffffffffu, mx1, 1));
        mx1 = fmaxf(mx1, __shfl_xor_sync(0xffffffffu, mx1, 2));

        float nm0 = fmaxf(m0r, mx0), nm1 = fmaxf(m1r, mx1);
        float co0 = __expf(m0r - nm0), co1 = __expf(m1r - nm1);
        m0r = nm0; m1r = nm1;

        uint32_t pp[8][2];
        float sl0 = 0.f, sl1 = 0.f;
#pragma unroll
        for (int j = 0; j < 8; j++) {
            float p00 = __expf(s[j][0] - nm0), p01 = __expf(s[j][1] - nm0);
            float p10 = __expf(s[j][2] - nm1), p11 = __expf(s[j][3] - nm1);
            sl0 += p00 + p01;  sl1 += p10 + p11;
            pp[j][0] = pack2_f16(p00, p01);
            pp[j][1] = pack2_f16(p10, p11);
        }
        sl0 += __shfl_xor_sync(0xffffffffu, sl0, 1);
        sl0 += __shfl_xor_sync(0xffffffffu, sl0, 2);
        sl1 += __shfl_xor_sync(0xffffffffu, sl1, 1);
        sl1 += __shfl_xor_sync(0xffffffffu, sl1, 2);
        l0r = l0r * co0 + sl0;
        l1r = l1r * co1 + sl1;
#pragma unroll
        for (int n = 0; n < 16; n++) {
            yacc[n][0] *= co0; yacc[n][1] *= co0;
            yacc[n][2] *= co1; yacc[n][3] *= co1;
        }

        // ---- V(kb) resident; make visible
        CP_WAIT(0);
        __syncthreads();

        // ---- O += P V
#pragma unroll
        for (int t = 0; t < 4; t++) {
            uint32_t ap[4] = {pp[2*t][0], pp[2*t][1], pp[2*t+1][0], pp[2*t+1][1]};
#pragma unroll
            for (int half = 0; half < 2; half++) {
                uint32_t vf[4][4];
#pragma unroll
                for (int nn = 0; nn < 4; nn++)
                    ldsm_x4_t(vf[nn], vaddr + t * (16 * FA_PITCH)
                                      + (half * 4 + nn) * 32);
#pragma unroll
                for (int nn = 0; nn < 4; nn++) {
                    int n2 = (half * 4 + nn) * 2;
                    mma16816(yacc[n2],     ap, vf[nn]);
                    mma16816(yacc[n2 + 1], ap, vf[nn] + 2);
                }
            }
        }
    }

    // ---- finalize: y/l as fp16 into [B,T,C] layout
    const float inv0 = 1.f / l0r, inv1 = 1.f / l1r;
    const int b = bh >> 4, h = bh & 15;
    const int t0 = qb * 64 + wid * 16 + r0;
    const size_t base0 = ((size_t)(b * TT + t0)) * CC + h * DD;
    const size_t base1 = base0 + (size_t)8 * CC;
#pragma unroll
    for (int n = 0; n < 16; n++) {
        int d0 = n * 8 + c0;
        *(uint32_t*)(g_y + base0 + d0) =
            pack2_f16(yacc[n][0] * inv0, yacc[n][1] * inv0);
        *(uint32_t*)(g_y + base1 + d0) =
            pack2_f16(yacc[n][2] * inv1, yacc[n][3] * inv1);
    }
}

// ============================================================================
extern "C" void kernel_launch(void* const* d_in, const int* in_sizes, int n_in,
                              void* d_out, int out_size)
{
    const float* x      = (const float*)d_in[0];   // [2,2048,2048]
    const float* w_attn = (const float*)d_in[1];   // [2048,6144]
    const float* w_proj = (const float*)d_in[2];   // [2048,2048]
    float* out = (float*)d_out;                    // [2,2048,2048]

    fp16 *xh, *yh, *wqh, *wph;
    cudaGetSymbolAddress((void**)&xh,  g_x);
    cudaGetSymbolAddress((void**)&yh,  g_y);
    cudaGetSymbolAddress((void**)&wqh, g_wq);
    cudaGetSymbolAddress((void**)&wph, g_wp);

    cudaFuncSetAttribute(gemm_fp16_kernel<0>,
                         cudaFuncAttributeMaxDynamicSharedMemorySize, GEMM_SMEM);
    cudaFuncSetAttribute(gemm_fp16_kernel<1>,
                         cudaFuncAttributeMaxDynamicSharedMemorySize, GEMM_SMEM);
    cudaFuncSetAttribute(flash_attn_mma_kernel,
                         cudaFuncAttributeMaxDynamicSharedMemorySize, FA_SMEM);

    // 0) fused prep: x conversion + both weight transposes in ONE launch
    prep_all_kernel<<<PREP_TOTAL, 256>>>(x, w_attn, w_proj);

    // 1) QKV projection -> fp16 q (pre-scaled), k, v  (round-8 config)
    gemm_fp16_kernel<0><<<dim3(N3C / 128, MTOT / 128), 256, GEMM_SMEM>>>(
        xh, wqh, nullptr);

    // 2) causal flash attention (mma.sync fp16) -> g_y
    flash_attn_mma_kernel<<<dim3(TT / 64, BB * HH), 128, FA_SMEM>>>();

    // 3) output projection -> out (fp32)
    gemm_fp16_kernel<1><<<dim3(CC / 128, MTOT / 128), 256, GEMM_SMEM>>>(
        yh, wph, out);
}

// round 16
// speedup vs baseline: 1.0973x; 1.0359x over previous
#include <cuda_runtime.h>
#include <cuda_fp16.h>
#include <math_constants.h>
#include <cstdint>

// Problem constants (B=2, T=2048, C=2048, H=16, D=128)
#define BB   2
#define TT   2048
#define CC   2048
#define HH   16
#define DD   128
#define MTOT (BB*TT)          // 4096
#define N3C  (3*CC)           // 6144
#define KDIM 2048

typedef __half fp16;

// -------- scratch (static device globals: the allowed scratch path) --------
__device__ fp16 g_q[(size_t)BB*HH*TT*DD];    // q pre-scaled by 1/sqrt(d)
__device__ fp16 g_k[(size_t)BB*HH*TT*DD];
__device__ fp16 g_v[(size_t)BB*HH*TT*DD];
__device__ fp16 g_x[(size_t)MTOT*KDIM];      // x as fp16
__device__ fp16 g_y[(size_t)MTOT*KDIM];      // attention out as fp16
__device__ fp16 g_wq[(size_t)N3C*KDIM];      // w_attn^T [N][K] fp16
__device__ fp16 g_wp[(size_t)CC*KDIM];       // w_proj^T [N][K] fp16
__device__ int  g_done[BB*32];               // [b][q64tile] head-completion count

// ============================================================================
// helpers
// ============================================================================
__device__ __forceinline__ uint32_t smem_u32(const void* p) {
    uint32_t a;
    asm("{ .reg .u64 t; cvta.to.shared.u64 t, %1; cvt.u32.u64 %0, t; }"
        : "=r"(a) : "l"(p));
    return a;
}
// (fp16(a) in low 16) | (fp16(b) in high 16)
__device__ __forceinline__ uint32_t pack2_f16(float a, float b) {
    uint32_t r;
    asm("cvt.rn.f16x2.f32 %0, %1, %2;" : "=r"(r) : "f"(b), "f"(a));
    return r;
}
#define CP16(dst, src) \
    asm volatile("cp.async.cg.shared.global [%0], [%1], 16;" \
                 :: "r"(dst), "l"(src))
#define CP_COMMIT() asm volatile("cp.async.commit_group;")
#define CP_WAIT(n)  asm volatile("cp.async.wait_group %0;" :: "n"(n))

__device__ __forceinline__ void ldsm_x4(uint32_t* r, uint32_t addr) {
    asm volatile("ldmatrix.sync.aligned.m8n8.x4.shared.b16 {%0,%1,%2,%3}, [%4];"
        : "=r"(r[0]), "=r"(r[1]), "=r"(r[2]), "=r"(r[3]) : "r"(addr));
}
__device__ __forceinline__ void ldsm_x4_t(uint32_t* r, uint32_t addr) {
    asm volatile("ldmatrix.sync.aligned.m8n8.x4.trans.shared.b16 {%0,%1,%2,%3}, [%4];"
        : "=r"(r[0]), "=r"(r[1]), "=r"(r[2]), "=r"(r[3]) : "r"(addr));
}
__device__ __forceinline__ void ldsm_x2(uint32_t* r, uint32_t addr) {
    asm volatile("ldmatrix.sync.aligned.m8n8.x2.shared.b16 {%0,%1}, [%2];"
        : "=r"(r[0]), "=r"(r[1]) : "r"(addr));
}
__device__ __forceinline__ void mma16816(float* c, const uint32_t* a,
                                         const uint32_t* b) {
    asm volatile(
        "mma.sync.aligned.m16n8k16.row.col.f32.f16.f16.f32 "
        "{%0,%1,%2,%3}, {%4,%5,%6,%7}, {%8,%9}, {%0,%1,%2,%3};"
        : "+f"(c[0]), "+f"(c[1]), "+f"(c[2]), "+f"(c[3])
        : "r"(a[0]), "r"(a[1]), "r"(a[2]), "r"(a[3]), "r"(b[0]), "r"(b[1]));
}

// ============================================================================
// Fused prep: ONE launch: x conversion + both weight transposes + flag reset.
// ============================================================================
#define PREP_CONV_BLKS 8192
#define PREP_WQ_BLKS   6144
#define PREP_WP_BLKS   2048
#define PREP_TOTAL     (PREP_CONV_BLKS + PREP_WQ_BLKS + PREP_WP_BLKS)

__device__ __forceinline__ void prep_w_body(
    const float* __restrict__ W, fp16* __restrict__ O, int N,
    int nblk, int kblk, int tid)
{
    __shared__ float s[32][65];
    const int k0 = kblk * 64;
    const int n0 = nblk * 32;
    const int nn = tid & 31, kk = tid >> 5;
#pragma unroll
    for (int i = 0; i < 8; i++) {
        int k = kk + i * 8;
        s[nn][k] = __ldg(W + (size_t)(k0 + k) * N + n0 + nn);
    }
    __syncthreads();
    const int n = tid >> 3, kc = (tid & 7) * 8;
    uint32_t o4[4];
#pragma unroll
    for (int j = 0; j < 4; j++)
        o4[j] = pack2_f16(s[n][kc + 2*j], s[n][kc + 2*j + 1]);
    size_t o = (size_t)(n0 + n) * KDIM + k0 + kc;
    *(uint4*)(O + o) = *(uint4*)o4;
}

__global__ __launch_bounds__(256) void prep_all_kernel(
    const float* __restrict__ X, const float* __restrict__ Wq,
    const float* __restrict__ Wp)
{
    const int b   = blockIdx.x;
    const int tid = threadIdx.x;
    if (b == 0 && tid < BB * 32) g_done[tid] = 0;   // reset dependency flags
    if (b < PREP_CONV_BLKS) {
        size_t i4 = (size_t)b * 256 + tid;
        float4 v = ((const float4*)X)[i4];
        uint32_t lo = pack2_f16(v.x, v.y);
        uint32_t hi = pack2_f16(v.z, v.w);
        *(uint2*)(g_x + i4 * 4) = make_uint2(lo, hi);
    } else if (b < PREP_CONV_BLKS + PREP_WQ_BLKS) {
        int lb = b - PREP_CONV_BLKS;
        prep_w_body(Wq, g_wq, N3C, lb % (N3C / 32), lb / (N3C / 32), tid);
    } else {
        int lb = b - PREP_CONV_BLKS - PREP_WQ_BLKS;
        prep_w_body(Wp, g_wp, CC, lb % (CC / 32), lb / (CC / 32), tid);
    }
}

// ============================================================================
// QKV GEMM via mma.sync (round-8 config, unchanged): 128x128x64, 256 thr.
// ============================================================================
#define GPITCH 144            // 64 fp16 = 128B + 16B pad
#define BOFF   18432          // 128 rows * 144B
#define STG    36864          // A + B
#define GEMM_SMEM (2*STG)     // 73728
#define NCHUNK (KDIM/64)      // 32

__global__ __launch_bounds__(256, 2) void gemm_qkv_kernel(
    const fp16* __restrict__ A, const fp16* __restrict__ B)
{
    extern __shared__ char smem[];
    const uint32_t sb = smem_u32(smem);
    const int tid  = threadIdx.x;
    const int lane = tid & 31, wid = tid >> 5;
    const int wm = wid & 1, wn = wid >> 1;       // warp grid 2 x 4
    const int m0 = blockIdx.y * 128;
    const int n0 = blockIdx.x * 128;

    float acc[4][4][4];
#pragma unroll
    for (int mi = 0; mi < 4; mi++)
#pragma unroll
        for (int ni = 0; ni < 4; ni++)
#pragma unroll
            for (int f = 0; f < 4; f++) acc[mi][ni][f] = 0.f;

    const uint32_t aBase = sb + (wm * 64 + (lane & 15)) * GPITCH
                         + (lane >> 4) * 16;
    const uint32_t bBase = sb + BOFF + (wn * 32 + (lane & 7)) * GPITCH
                         + ((lane >> 3) & 1) * 16;

#define LOAD_CHUNK(c, st) do {                                                 \
    uint32_t s0 = sb + (st) * STG;                                             \
    _Pragma("unroll")                                                          \
    for (int p = 0; p < 4; p++) {                                              \
        int o   = tid + p * 256;                                               \
        int row = o >> 3, ch = o & 7;                                          \
        uint32_t dofs = row * GPITCH + ch * 16;                                \
        size_t ga = (size_t)(m0 + row) * KDIM + (c) * 64 + ch * 8;             \
        size_t gb = (size_t)(n0 + row) * KDIM + (c) * 64 + ch * 8;             \
        CP16(s0 + dofs, A + ga);                                               \
        CP16(s0 + BOFF + dofs, B + gb);                                        \
    }                                                                          \
} while (0)

    LOAD_CHUNK(0, 0);
    CP_COMMIT();

    for (int c = 0; c < NCHUNK; c++) {
        const int st = c & 1;
        CP_WAIT(0);
        __syncthreads();
        if (c + 1 < NCHUNK) {
            LOAD_CHUNK(c + 1, st ^ 1);
            CP_COMMIT();
        }
        const uint32_t sStage = st * STG;
#pragma unroll
        for (int ks = 0; ks < 4; ks++) {
            const uint32_t kOfs = sStage + ks * 32;
            uint32_t aw[4][4], bw[4][2];
#pragma unroll
            for (int mi = 0; mi < 4; mi++)
                ldsm_x4(aw[mi], aBase + kOfs + mi * (16 * GPITCH));
#pragma unroll
            for (int ni = 0; ni < 4; ni++)
                ldsm_x2(bw[ni], bBase + kOfs + ni * (8 * GPITCH));
#pragma unroll
            for (int mi = 0; mi < 4; mi++)
#pragma unroll
                for (int ni = 0; ni < 4; ni++)
                    mma16816(acc[mi][ni], aw[mi], bw[ni]);
        }
    }
#undef LOAD_CHUNK

    const int lr = lane >> 2, lc = (lane & 3) * 2;
#pragma unroll
    for (int mi = 0; mi < 4; mi++) {
#pragma unroll
        for (int ni = 0; ni < 4; ni++) {
            int mrow = m0 + wm * 64 + mi * 16 + lr;
            int col  = wn * 32 + ni * 8 + lc;
            const int nb = blockIdx.x;
            const int which = nb >> 4, head = nb & 15;
            const float sc = (which == 0) ? 0.08838834764831845f : 1.0f;
            fp16* base = (which == 0) ? g_q : (which == 1) ? g_k : g_v;
            int b0 = mrow >> 11, t0 = mrow & 2047;
            int m1 = mrow + 8;
            int b1 = m1 >> 11, t1 = m1 & 2047;
            size_t i0 = ((size_t)((b0 * HH + head) * TT + t0)) * DD + col;
            size_t i1 = ((size_t)((b1 * HH + head) * TT + t1)) * DD + col;
            *(uint32_t*)(base + i0) =
                pack2_f16(acc[mi][ni][0] * sc, acc[mi][ni][1] * sc);
            *(uint32_t*)(base + i1) =
                pack2_f16(acc[mi][ni][2] * sc, acc[mi][ni][3] * sc);
        }
    }
}

// ============================================================================
// FUSED attention + output projection, one launch, 128 threads/block.
//   bids [0, 1024):    FA role (round-8 FA; publishes g_done per q-tile)
//   bids [1024, 1536): proj role (4 warps, 64x64 warp tile; spins on flags)
// ============================================================================
#define FA_PITCH 272
#define FA_K0 0
#define FA_K1 17408
#define FA_V  34816
#define FUSED_SMEM 73728      // max(FA 52224, proj 73728); x2 = 147456/SM

#define FA_BLOCKS  (32 * BB * HH)   // 1024
#define PJ_BLOCKS  ((MTOT / 128) * (CC / 128))   // 512

__device__ __forceinline__ void fa_role(int fid, char* smc)
{
    const uint32_t sb = smem_u32(smc);
    const int tid  = threadIdx.x;
    const int lane = tid & 31, wid = tid >> 5;
    const int bh = fid >> 5;
    const int qb = 31 - (fid & 31);            // longest CTAs first
    const int b  = bh >> 4, h = bh & 15;

    const size_t bhofs = (size_t)bh * TT * DD;
    const fp16* Qg = g_q + bhofs + (size_t)qb * 64 * DD;

#pragma unroll
    for (int p = 0; p < 8; p++) {
        int o = tid + p * 128;
        int row = o >> 4, ch = o & 15;
        uint32_t d = row * FA_PITCH + ch * 16;
        size_t g = (size_t)row * DD + ch * 8;
        CP16(sb + FA_K1 + d, Qg + g);
        CP16(sb + FA_K0 + d, g_k + bhofs + g);
    }
    CP_COMMIT();
    CP_WAIT(0);
    __syncthreads();

    uint32_t qf[8][4];
    {
        uint32_t qa = sb + FA_K1 + (wid * 16 + (lane & 15)) * FA_PITCH
                    + (lane >> 4) * 16;
#pragma unroll
        for (int ks = 0; ks < 8; ks++)
            ldsm_x4(qf[ks], qa + ks * 32);
    }

    float yacc[16][4];
#pragma unroll
    for (int n = 0; n < 16; n++)
#pragma unroll
        for (int f = 0; f < 4; f++) yacc[n][f] = 0.f;
    float m0r = -CUDART_INF_F, m1r = -CUDART_INF_F;
    float l0r = 0.f, l1r = 0.f;

    const int r0 = lane >> 2;
    const int c0 = (lane & 3) * 2;
    const uint32_t laneK = ((lane & 7) + ((lane >> 4) & 1) * 8) * FA_PITCH
                         + ((lane >> 3) & 1) * 16;
    const uint32_t vaddr = sb + FA_V
        + ((lane & 7) + ((lane >> 3) & 1) * 8) * FA_PITCH
        + ((lane >> 4) & 1) * 16;

    for (int kb = 0; kb <= qb; kb++) {
        const uint32_t kaddr = sb + ((kb & 1) ? FA_K1 : FA_K0) + laneK;
        __syncthreads();
        {
            const fp16* Vg = g_v + bhofs + (size_t)kb * 64 * DD;
#pragma unroll
            for (int p = 0; p < 8; p++) {
                int o = tid + p * 128;
                int row = o >> 4, ch = o & 15;
                uint32_t d = row * FA_PITCH + ch * 16;
                size_t g = (size_t)row * DD + ch * 8;
                CP16(sb + FA_V + d, Vg + g);
            }
            if (kb < qb) {
                const uint32_t knext = sb + (((kb + 1) & 1) ? FA_K1 : FA_K0);
                const fp16* Kg = g_k + bhofs + (size_t)(kb + 1) * 64 * DD;
#pragma unroll
                for (int p = 0; p < 8; p++) {
                    int o = tid + p * 128;
                    int row = o >> 4, ch = o & 15;
                    uint32_t d = row * FA_PITCH + ch * 16;
                    size_t g = (size_t)row * DD + ch * 8;
                    CP16(knext + d, Kg + g);
                }
            }
            CP_COMMIT();
        }

        float s[8][4];
#pragma unroll
        for (int j = 0; j < 8; j++)
#pragma unroll
            for (int f = 0; f < 4; f++) s[j][f] = 0.f;
#pragma unroll
        for (int ks = 0; ks < 8; ks++) {
            uint32_t kf[4][4];
#pragma unroll
            for (int jj = 0; jj < 4; jj++)
                ldsm_x4(kf[jj], kaddr + jj * (16 * FA_PITCH) + ks * 32);
#pragma unroll
            for (int jj = 0; jj < 4; jj++) {
                mma16816(s[2*jj],   qf[ks], kf[jj]);
                mma16816(s[2*jj+1], qf[ks], kf[jj] + 2);
            }
        }

        if (kb == qb) {
            const int rg0 = wid * 16 + r0;
#pragma unroll
            for (int j = 0; j < 8; j++) {
                int cg = j * 8 + c0;
                if (cg     > rg0)     s[j][0] = -CUDART_INF_F;
                if (cg + 1 > rg0)     s[j][1] = -CUDART_INF_F;
                if (cg     > rg0 + 8) s[j][2] = -CUDART_INF_F;
                if (cg + 1 > rg0 + 8) s[j][3] = -CUDART_INF_F;
            }
        }

        float mx0 = -CUDART_INF_F, mx1 = -CUDART_INF_F;
#pragma unroll
        for (int j = 0; j < 8; j++) {
            mx0 = fmaxf(mx0, fmaxf(s[j][0], s[j][1]));
            mx1 = fmaxf(mx1, fmaxf(s[j][2], s[j][3]));
        }
        mx0 = fmaxf(mx0, __shfl_xor_sync(0xffffffffu, mx0, 1));
        mx0 = fmaxf(mx0, __shfl_xor_sync(0xffffffffu, mx0, 2));
        mx1 = fmaxf(mx1, __shfl_xor_sync(0xffffffffu, mx1, 1));
        mx1 = fmaxf(mx1, __shfl_xor_sync(0xffffffffu, mx1, 2));

        float nm0 = fmaxf(m0r, mx0), nm1 = fmaxf(m1r, mx1);
        float co0 = __expf(m0r - nm0), co1 = __expf(m1r - nm1);
        m0r = nm0; m1r = nm1;

        uint32_t pp[8][2];
        float sl0 = 0.f, sl1 = 0.f;
#pragma unroll
        for (int j = 0; j < 8; j++) {
            float p00 = __expf(s[j][0] - nm0), p01 = __expf(s[j][1] - nm0);
            float p10 = __expf(s[j][2] - nm1), p11 = __expf(s[j][3] - nm1);
            sl0 += p00 + p01;  sl1 += p10 + p11;
            pp[j][0] = pack2_f16(p00, p01);
            pp[j][1] = pack2_f16(p10, p11);
        }
        sl0 += __shfl_xor_sync(0xffffffffu, sl0, 1);
        sl0 += __shfl_xor_sync(0xffffffffu, sl0, 2);
        sl1 += __shfl_xor_sync(0xffffffffu, sl1, 1);
        sl1 += __shfl_xor_sync(0xffffffffu, sl1, 2);
        l0r = l0r * co0 + sl0;
        l1r = l1r * co1 + sl1;
#pragma unroll
        for (int n = 0; n < 16; n++) {
            yacc[n][0] *= co0; yacc[n][1] *= co0;
            yacc[n][2] *= co1; yacc[n][3] *= co1;
        }

        CP_WAIT(0);
        __syncthreads();

#pragma unroll
        for (int t = 0; t < 4; t++) {
            uint32_t ap[4] = {pp[2*t][0], pp[2*t][1], pp[2*t+1][0], pp[2*t+1][1]};
#pragma unroll
            for (int half = 0; half < 2; half++) {
                uint32_t vf[4][4];
#pragma unroll
                for (int nn = 0; nn < 4; nn++)
                    ldsm_x4_t(vf[nn], vaddr + t * (16 * FA_PITCH)
                                      + (half * 4 + nn) * 32);
#pragma unroll
                for (int nn = 0; nn < 4; nn++) {
                    int n2 = (half * 4 + nn) * 2;
                    mma16816(yacc[n2],     ap, vf[nn]);
                    mma16816(yacc[n2 + 1], ap, vf[nn] + 2);
                }
            }
        }
    }

    const float inv0 = 1.f / l0r, inv1 = 1.f / l1r;
    const int t0 = qb * 64 + wid * 16 + r0;
    const size_t base0 = ((size_t)(b * TT + t0)) * CC + h * DD;
    const size_t base1 = base0 + (size_t)8 * CC;
#pragma unroll
    for (int n = 0; n < 16; n++) {
        int d0 = n * 8 + c0;
        *(uint32_t*)(g_y + base0 + d0) =
            pack2_f16(yacc[n][0] * inv0, yacc[n][1] * inv0);
        *(uint32_t*)(g_y + base1 + d0) =
            pack2_f16(yacc[n][2] * inv1, yacc[n][3] * inv1);
    }

    // publish: g_y rows for (b, qb) by this head are visible
    __threadfence();
    __syncthreads();
    if (tid == 0) atomicAdd(&g_done[b * 32 + qb], 1);
}

__device__ __forceinline__ void proj_role(int pid, char* smc,
                                          float* __restrict__ Cout)
{
    const uint32_t sb = smem_u32(smc);
    const int tid  = threadIdx.x;
    const int lane = tid & 31, wid = tid >> 5;   // 4 warps
    const int wm = wid >> 1, wn = wid & 1;       // warp grid 2 x 2
    const int m0 = (pid >> 4) * 128;             // 32 m-tiles
    const int n0 = (pid & 15) * 128;             // 16 n-tiles

    // ---- wait until all 16 heads wrote g_y for this 128-token range
    {
        const int b  = m0 >> 11;
        const int q0 = (m0 & 2047) >> 6;         // two 64-token tiles
        if (tid == 0) {
            volatile int* f0 = &g_done[b * 32 + q0];
            volatile int* f1 = &g_done[b * 32 + q0 + 1];
            while (*f0 < HH || *f1 < HH) __nanosleep(200);
        }
        __syncthreads();
        __threadfence();                          // order reads after flags
    }

    const fp16* A = g_y;
    const fp16* B = g_wp;

    float acc[4][8][4];
#pragma unroll
    for (int mi = 0; mi < 4; mi++)
#pragma unroll
        for (int nj = 0; nj < 8; nj++)
#pragma unroll
            for (int f = 0; f < 4; f++) acc[mi][nj][f] = 0.f;

    const uint32_t aBase = sb + (wm * 64 + (lane & 15)) * GPITCH
                         + (lane >> 4) * 16;
    const uint32_t bBase = sb + BOFF
        + (wn * 64 + (lane & 7) + ((lane >> 4) & 1) * 8) * GPITCH
        + ((lane >> 3) & 1) * 16;

#define PLOAD_CHUNK(c, st) do {                                                \
    uint32_t s0 = sb + (st) * STG;                                             \
    _Pragma("unroll")                                                          \
    for (int p = 0; p < 8; p++) {                                              \
        int o   = tid + p * 128;          /* 0..1023 */                        \
        int row = o >> 3, ch = o & 7;                                          \
        uint32_t dofs = row * GPITCH + ch * 16;                                \
        size_t ga = (size_t)(m0 + row) * KDIM + (c) * 64 + ch * 8;             \
        size_t gb = (size_t)(n0 + row) * KDIM + (c) * 64 + ch * 8;             \
        CP16(s0 + dofs, A + ga);                                               \
        CP16(s0 + BOFF + dofs, B + gb);                                        \
    }                                                                          \
} while (0)

    PLOAD_CHUNK(0, 0);
    CP_COMMIT();

    for (int c = 0; c < NCHUNK; c++) {
        const int st = c & 1;
        CP_WAIT(0);
        __syncthreads();
        if (c + 1 < NCHUNK) {
            PLOAD_CHUNK(c + 1, st ^ 1);
            CP_COMMIT();
        }
        const uint32_t sStage = st * STG;
#pragma unroll
        for (int ks = 0; ks < 4; ks++) {
            const uint32_t kOfs = sStage + ks * 32;
            uint32_t aw[4][4], bw[4][4];
#pragma unroll
            for (int mi = 0; mi < 4; mi++)
                ldsm_x4(aw[mi], aBase + kOfs + mi * (16 * GPITCH));
#pragma unroll
            for (int nj = 0; nj < 4; nj++)
                ldsm_x4(bw[nj], bBase + kOfs + nj * (16 * GPITCH));
#pragma unroll
            for (int mi = 0; mi < 4; mi++)
#pragma unroll
                for (int nj = 0; nj < 4; nj++) {
                    mma16816(acc[mi][2*nj],     aw[mi], bw[nj]);
                    mma16816(acc[mi][2*nj + 1], aw[mi], bw[nj] + 2);
                }
        }
    }
#undef PLOAD_CHUNK

    const int lr = lane >> 2, lc = (lane & 3) * 2;
#pragma unroll
    for (int mi = 0; mi < 4; mi++) {
#pragma unroll
        for (int nj = 0; nj < 8; nj++) {
            int mrow = m0 + wm * 64 + mi * 16 + lr;
            int col  = wn * 64 + nj * 8 + lc;
            float* p0 = Cout + (size_t)mrow * CC + n0 + col;
            float* p1 = p0 + (size_t)8 * CC;
            *(float2*)p0 = make_float2(acc[mi][nj][0], acc[mi][nj][1]);
            *(float2*)p1 = make_float2(acc[mi][nj][2], acc[mi][nj][3]);
        }
    }
}

__global__ __launch_bounds__(128, 2) void fused_attn_proj_kernel(
    float* __restrict__ Cout)
{
    extern __shared__ char smc[];
    const int bid = blockIdx.x;
    if (bid < FA_BLOCKS) fa_role(bid, smc);
    else                 proj_role(bid - FA_BLOCKS, smc, Cout);
}

// ============================================================================
extern "C" void kernel_launch(void* const* d_in, const int* in_sizes, int n_in,
                              void* d_out, int out_size)
{
    const float* x      = (const float*)d_in[0];   // [2,2048,2048]
    const float* w_attn = (const float*)d_in[1];   // [2048,6144]
    const float* w_proj = (const float*)d_in[2];   // [2048,2048]
    float* out = (float*)d_out;                    // [2,2048,2048]

    fp16 *xh, *wqh;
    cudaGetSymbolAddress((void**)&xh,  g_x);
    cudaGetSymbolAddress((void**)&wqh, g_wq);

    cudaFuncSetAttribute(gemm_qkv_kernel,
                         cudaFuncAttributeMaxDynamicSharedMemorySize, GEMM_SMEM);
    cudaFuncSetAttribute(fused_attn_proj_kernel,
                         cudaFuncAttributeMaxDynamicSharedMemorySize, FUSED_SMEM);

    // 0) fused prep: x conversion + weight transposes + flag reset
    prep_all_kernel<<<PREP_TOTAL, 256>>>(x, w_attn, w_proj);

    // 1) QKV projection -> fp16 q (pre-scaled), k, v
    gemm_qkv_kernel<<<dim3(N3C / 128, MTOT / 128), 256, GEMM_SMEM>>>(xh, wqh);

    // 2) FUSED: causal flash attention + output projection (software deps)
    fused_attn_proj_kernel<<<FA_BLOCKS + PJ_BLOCKS, 128, FUSED_SMEM>>>(out);
}